// round 7
// baseline (speedup 1.0000x reference)
#include <cuda_runtime.h>
#include <cuda_bf16.h>
#include <math.h>

// AssociativeLIF forward: T=8, B=128, D=8192, NC=64
// d_out = [ ss (T,B,D) | vt (T,B,D) ] float32
// Layout: thread owns d = 4*tid + j  (h=0)  and  d = 4*tid + 4096 + j (h=1), j=0..3
//   -> two float4 per thread, fully coalesced 128-bit I/O
//   -> cluster of d (when cids[d]==d%64) is 4*(tid&15)+j for BOTH halves

#define T_STEPS 8
#define BATCH   128
#define DIM     8192
#define NC      64
#define TPB     1024
#define V_RESET (-0.1f)
#define REF_T   2

__global__ __launch_bounds__(TPB, 1)
void assoc_lif_kernel(const float* __restrict__ x,        // [T,B,D]
                      const float* __restrict__ th_raw,   // [D]
                      const float* __restrict__ bm_raw,   // [1]
                      const float* __restrict__ bs_raw,   // [1]
                      const float* __restrict__ nw,       // [NC,NC]
                      const float* __restrict__ gain,     // [NC]
                      const int*   __restrict__ cids,     // [D]
                      float* __restrict__ out_s,          // [T,B,D]
                      float* __restrict__ out_v)          // [T,B,D]
{
    __shared__ float Wts[NC * NC];              // Wts[j*64+c] = sigmoid(nw[c][j]) / 128 (exact)
    __shared__ float g_sm[NC];
    __shared__ unsigned cnt[2][16];             // packed byte counts, double-buffered
    __shared__ float cf_slow[2][NC];            // fallback float counts
    __shared__ __align__(16) float ns[NC];
    __shared__ float bm_sh, bs_sh;

    const int b   = blockIdx.x;
    const int tid = threadIdx.x;

    // ---- one-time parameter prep ----
    for (int idx = tid; idx < NC * NC; idx += TPB) {
        int c = idx >> 6, j = idx & 63;                     // nw row-major [c][j]
        Wts[j * NC + c] = (1.0f / (1.0f + expf(-nw[idx]))) * (1.0f / 128.0f);
    }
    if (tid < NC)      g_sm[tid] = gain[tid];
    if (tid < 32)      ((unsigned*)cnt)[tid] = 0u;
    if (tid < 2 * NC)  ((float*)cf_slow)[tid] = 0.0f;
    if (tid == 0) {
        float bm = 1.0f / (1.0f + expf(-bm_raw[0]));
        bm_sh = fminf(fmaxf(bm, 0.8f), 0.98f);
        bs_sh = 1.0f / (1.0f + expf(-bs_raw[0]));
    }

    // fast path iff cids[d] == d % 64 for this thread's 8 neurons
    bool okf = true;
    #pragma unroll
    for (int j = 0; j < 4; j++) {
        okf &= (cids[4 * tid + j]        == ((4 * tid + j) & 63));
        okf &= (cids[4 * tid + 4096 + j] == ((4 * tid + j) & 63));
    }
    const bool fast = (__syncthreads_and((int)okf) != 0);   // also fences smem init

    const float bm = bm_sh, bs = bs_sh, om = 1.0f - bm;

    const size_t bd    = (size_t)b * DIM;
    const size_t step  = (size_t)BATCH * DIM;
    const size_t step4 = step / 4;

    const float4* x4 = (const float4*)(x     + bd);
    float4*       s4 = (float4*)      (out_s + bd);
    float4*       v4 = (float4*)      (out_v + bd);

    // ---- per-thread state ----
    float v[8], isyn[8], th[8], xv[8];
    unsigned rp = 0;                    // refractory, 2 bits/neuron
    {
        const float4* t4 = (const float4*)th_raw;
        float4 t0 = t4[tid], t1 = t4[tid + 1024];
        th[0]=t0.x; th[1]=t0.y; th[2]=t0.z; th[3]=t0.w;
        th[4]=t1.x; th[5]=t1.y; th[6]=t1.z; th[7]=t1.w;
        #pragma unroll
        for (int k = 0; k < 8; k++) {
            th[k] = fminf(fmaxf(th[k], 0.05f), 0.5f);
            v[k] = 0.0f; isyn[k] = 0.0f;
        }
        float4 a = x4[tid], c = x4[tid + 1024];   // preload t=0
        xv[0]=a.x; xv[1]=a.y; xv[2]=a.z; xv[3]=a.w;
        xv[4]=c.x; xv[5]=c.y; xv[6]=c.z; xv[7]=c.w;
    }

    for (int t = 0; t < T_STEPS; t++) {
        const int buf = t & 1;

        // ---- LIF update + spike ----
        unsigned smask = 0;
        #pragma unroll
        for (int k = 0; k < 8; k++) {
            isyn[k] = bs * isyn[k] + xv[k];
            float nv = bm * v[k] + om * isyn[k];
            int refr = (rp >> (2 * k)) & 3;
            v[k] = (refr > 0) ? V_RESET : nv;
            if (v[k] >= th[k]) smask |= (1u << k);
        }

        // ---- spike counting ----
        if (fast) {
            // bits k=h*4+j -> cluster 4*(tid&15)+j ; expand bits to bytes, sum halves
            unsigned m0 = smask & 0xFu, m1 = (smask >> 4) & 0xFu;
            unsigned packed = ((m0 * 0x00204081u) & 0x01010101u)
                            + ((m1 * 0x00204081u) & 0x01010101u);
            packed += __shfl_xor_sync(0xFFFFFFFFu, packed, 16);
            if ((tid & 31) < 16 && packed)
                atomicAdd(&cnt[buf][tid & 15], packed);   // byte c&3 of word c>>2, max 128
        } else {
            #pragma unroll
            for (int k = 0; k < 8; k++)
                if (smask & (1u << k)) {
                    int d = 4 * tid + (k & 3) + (k >> 2) * 4096;
                    atomicAdd(&cf_slow[buf][__ldg(&cids[d])], 1.0f);
                }
        }

        // ---- prefetch next x (hide DRAM latency behind cascade) ----
        if (t + 1 < T_STEPS) {
            const float4* xn = x4 + (size_t)(t + 1) * step4;
            float4 a = xn[tid], c = xn[tid + 1024];
            xv[0]=a.x; xv[1]=a.y; xv[2]=a.z; xv[3]=a.w;
            xv[4]=c.x; xv[5]=c.y; xv[6]=c.z; xv[7]=c.w;
        }

        // ---- reset, refractory, stores (independent of cascade result) ----
        unsigned rp_new = 0;
        float sv[8];
        #pragma unroll
        for (int k = 0; k < 8; k++) {
            float sk = (smask & (1u << k)) ? 1.0f : 0.0f;
            sv[k] = sk;
            v[k] -= sk * th[k];
            int refr = (rp >> (2 * k)) & 3;
            int nr = (smask & (1u << k)) ? REF_T : (refr > 0 ? refr - 1 : 0);
            rp_new |= (unsigned)nr << (2 * k);
        }
        rp = rp_new;
        {
            float4* st = s4 + (size_t)t * step4;
            float4* vt = v4 + (size_t)t * step4;
            st[tid]        = make_float4(sv[0], sv[1], sv[2], sv[3]);
            st[tid + 1024] = make_float4(sv[4], sv[5], sv[6], sv[7]);
            vt[tid]        = make_float4(v[0], v[1], v[2], v[3]);
            vt[tid + 1024] = make_float4(v[4], v[5], v[6], v[7]);
        }

        __syncthreads();   // counts complete

        // ---- 64-thread neighbor mix ----
        if (tid < NC) {
            float a0 = 0.f, a1 = 0.f, a2 = 0.f, a3 = 0.f;
            if (fast) {
                #pragma unroll
                for (int w = 0; w < 16; w++) {
                    unsigned u = cnt[buf][w];
                    // byte i -> float via PRMT(0x4B bias) + FADD
                    float f0 = __uint_as_float(__byte_perm(u, 0x4B000000u, 0x7540)) - 8388608.0f;
                    float f1 = __uint_as_float(__byte_perm(u, 0x4B000000u, 0x7541)) - 8388608.0f;
                    float f2 = __uint_as_float(__byte_perm(u, 0x4B000000u, 0x7542)) - 8388608.0f;
                    float f3 = __uint_as_float(__byte_perm(u, 0x4B000000u, 0x7543)) - 8388608.0f;
                    a0 += f0 * Wts[(4 * w + 0) * NC + tid];
                    a1 += f1 * Wts[(4 * w + 1) * NC + tid];
                    a2 += f2 * Wts[(4 * w + 2) * NC + tid];
                    a3 += f3 * Wts[(4 * w + 3) * NC + tid];
                }
            } else {
                #pragma unroll
                for (int j = 0; j < NC; j += 4) {
                    a0 += cf_slow[buf][j + 0] * Wts[(j + 0) * NC + tid];
                    a1 += cf_slow[buf][j + 1] * Wts[(j + 1) * NC + tid];
                    a2 += cf_slow[buf][j + 2] * Wts[(j + 2) * NC + tid];
                    a3 += cf_slow[buf][j + 3] * Wts[(j + 3) * NC + tid];
                }
            }
            ns[tid] = ((a0 + a1) + (a2 + a3)) * g_sm[tid];
            cf_slow[buf ^ 1][tid] = 0.0f;                 // consumed two syncs ago
        }
        if (tid < 16) cnt[buf ^ 1][tid] = 0u;

        __syncthreads();   // ns ready, next buffers zeroed

        // ---- apply cascade to i_syn ----
        if (fast) {
            float4 nsv = *(const float4*)&ns[4 * (tid & 15)];
            isyn[0] += nsv.x; isyn[1] += nsv.y; isyn[2] += nsv.z; isyn[3] += nsv.w;
            isyn[4] += nsv.x; isyn[5] += nsv.y; isyn[6] += nsv.z; isyn[7] += nsv.w;
        } else {
            #pragma unroll
            for (int k = 0; k < 8; k++) {
                int d = 4 * tid + (k & 3) + (k >> 2) * 4096;
                isyn[k] += ns[__ldg(&cids[d])];
            }
        }
    }
}

extern "C" void kernel_launch(void* const* d_in, const int* in_sizes, int n_in,
                              void* d_out, int out_size)
{
    const float* x      = (const float*)d_in[0];   // current_in [T,B,D]
    const float* th_raw = (const float*)d_in[1];   // threshold_raw [D]
    const float* bm_raw = (const float*)d_in[2];   // beta_mem_raw
    const float* bs_raw = (const float*)d_in[3];   // beta_syn_raw
    const float* nw     = (const float*)d_in[4];   // neighbor_weights [NC,NC]
    const float* gain   = (const float*)d_in[5];   // cluster_gain [NC]
    const int*   cids   = (const int*)d_in[6];     // cluster_ids [D]

    float* out_s = (float*)d_out;
    float* out_v = out_s + (size_t)T_STEPS * BATCH * DIM;

    assoc_lif_kernel<<<BATCH, TPB>>>(x, th_raw, bm_raw, bs_raw, nw, gain, cids,
                                     out_s, out_v);
}

// round 10
// speedup vs baseline: 1.2436x; 1.2436x over previous
#include <cuda_runtime.h>
#include <cuda_bf16.h>
#include <math.h>

// AssociativeLIF forward: T=8, B=128, D=8192, NC=64
// d_out = [ ss (T,B,D) | vt (T,B,D) ] float32
// Thread owns d = 4*tid + j (h=0) and d = 4*tid + 4096 + j (h=1), j=0..3.
// Fast path (cids[d] == d%64): thread's 8 neurons hit clusters 4*(tid&15)+j.

#define T_STEPS 8
#define BATCH   128
#define DIM     8192
#define NC      64
#define TPB     1024
#define V_RESET (-0.1f)

__global__ __launch_bounds__(TPB, 1)
void assoc_lif_kernel(const float* __restrict__ x,        // [T,B,D]
                      const float* __restrict__ th_raw,   // [D]
                      const float* __restrict__ bm_raw,   // [1]
                      const float* __restrict__ bs_raw,   // [1]
                      const float* __restrict__ nw,       // [NC,NC]
                      const float* __restrict__ gain,     // [NC]
                      const int*   __restrict__ cids,     // [D]
                      float* __restrict__ out_s,          // [T,B,D]
                      float* __restrict__ out_v)          // [T,B,D]
{
    __shared__ float Wts[NC * NC];          // Wts[j*64+c] = sigmoid(nw[c][j]) / 128 (exact scale)
    __shared__ float g_sm[NC];
    __shared__ unsigned cnt[2][16];         // packed byte counts (fast), double-buffered
    __shared__ float cf_slow[2][NC];        // fallback float counts
    __shared__ float partial[16][NC];       // distributed-dot partials
    __shared__ __align__(16) float ns[NC];
    __shared__ float bm_sh, bs_sh;

    const int b   = blockIdx.x;
    const int tid = threadIdx.x;

    // ---- one-time parameter prep ----
    for (int idx = tid; idx < NC * NC; idx += TPB) {
        int c = idx >> 6, j = idx & 63;                     // nw row-major [c][j]
        Wts[j * NC + c] = (1.0f / (1.0f + expf(-nw[idx]))) * (1.0f / 128.0f);
    }
    if (tid < NC)      g_sm[tid] = gain[tid];
    if (tid < 32)      ((unsigned*)cnt)[tid] = 0u;
    if (tid < 2 * NC)  ((float*)cf_slow)[tid] = 0.0f;
    if (tid == 0) {
        float bm = 1.0f / (1.0f + expf(-bm_raw[0]));
        bm_sh = fminf(fmaxf(bm, 0.8f), 0.98f);
        bs_sh = 1.0f / (1.0f + expf(-bs_raw[0]));
    }

    // fast path iff cids[d] == d % 64 for this thread's 8 neurons
    bool okf = true;
    #pragma unroll
    for (int j = 0; j < 4; j++) {
        okf &= (cids[4 * tid + j]        == ((4 * tid + j) & 63));
        okf &= (cids[4 * tid + 4096 + j] == ((4 * tid + j) & 63));
    }
    const bool fast = (__syncthreads_and((int)okf) != 0);   // also fences smem init

    const float bm = bm_sh, bs = bs_sh, om = 1.0f - bm;

    const size_t bd    = (size_t)b * DIM;
    const size_t step4 = (size_t)BATCH * DIM / 4;

    const float4* x4 = (const float4*)(x     + bd) + tid;
    float4*       s4 = (float4*)      (out_s + bd) + tid;
    float4*       v4 = (float4*)      (out_v + bd) + tid;

    // ---- per-thread state ----
    float v[8], isyn[8], th[8], xv[8];
    unsigned s1 = 0, s2 = 0;            // spike masks at t-1, t-2 (refractory)
    {
        const float4* t4 = (const float4*)th_raw;
        float4 t0 = t4[tid], t1 = t4[tid + 1024];
        th[0]=t0.x; th[1]=t0.y; th[2]=t0.z; th[3]=t0.w;
        th[4]=t1.x; th[5]=t1.y; th[6]=t1.z; th[7]=t1.w;
        #pragma unroll
        for (int k = 0; k < 8; k++) {
            th[k] = fminf(fmaxf(th[k], 0.05f), 0.5f);
            v[k] = 0.0f; isyn[k] = 0.0f;
        }
        float4 a = x4[0], c = x4[1024];             // preload t=0
        xv[0]=a.x; xv[1]=a.y; xv[2]=a.z; xv[3]=a.w;
        xv[4]=c.x; xv[5]=c.y; xv[6]=c.z; xv[7]=c.w;
    }

    for (int t = 0; t < T_STEPS; t++) {
        const int buf = t & 1;

        // ---- LIF update + spike (refrac>0 <=> spiked at t-1 or t-2) ----
        const unsigned refr = s1 | s2;
        unsigned smask = 0;
        #pragma unroll
        for (int k = 0; k < 8; k++) {
            isyn[k] = fmaf(bs, isyn[k], xv[k]);
            float nv = fmaf(bm, v[k], om * isyn[k]);
            v[k] = ((refr >> k) & 1u) ? V_RESET : nv;
            if (v[k] >= th[k]) smask |= (1u << k);
        }
        s2 = s1; s1 = smask;

        // ---- spike counting (parallel, pre-barrier) ----
        if (fast) {
            unsigned m0 = smask & 0xFu, m1 = (smask >> 4) & 0xFu;
            unsigned packed = ((m0 * 0x00204081u) & 0x01010101u)
                            + ((m1 * 0x00204081u) & 0x01010101u);
            packed += __shfl_xor_sync(0xFFFFFFFFu, packed, 16);
            if ((tid & 31) < 16 && packed)
                atomicAdd(&cnt[buf][tid & 15], packed);   // byte c&3 of word c>>2
        } else {
            #pragma unroll
            for (int k = 0; k < 8; k++)
                if (smask & (1u << k)) {
                    int d = 4 * tid + (k & 3) + (k >> 2) * 4096;
                    atomicAdd(&cf_slow[buf][__ldg(&cids[d])], 1.0f);
                }
        }

        // ---- prefetch next x (hidden behind cascade barriers) ----
        if (t + 1 < T_STEPS) {
            const float4* xn = x4 + (size_t)(t + 1) * step4;
            float4 a = __ldg(xn), c = __ldg(xn + 1024);
            xv[0]=a.x; xv[1]=a.y; xv[2]=a.z; xv[3]=a.w;
            xv[4]=c.x; xv[5]=c.y; xv[6]=c.z; xv[7]=c.w;
        }

        // ---- reset + streaming stores (independent of cascade) ----
        {
            float sv[8];
            #pragma unroll
            for (int k = 0; k < 8; k++) {
                float sk = (smask >> k) & 1u ? 1.0f : 0.0f;
                sv[k] = sk;
                v[k] = fmaf(-sk, th[k], v[k]);
            }
            float4* st = s4 + (size_t)t * step4;
            float4* vt = v4 + (size_t)t * step4;
            __stcs(st,        make_float4(sv[0], sv[1], sv[2], sv[3]));
            __stcs(st + 1024, make_float4(sv[4], sv[5], sv[6], sv[7]));
            __stcs(vt,        make_float4(v[0], v[1], v[2], v[3]));
            __stcs(vt + 1024, make_float4(v[4], v[5], v[6], v[7]));
        }

        __syncthreads();   // counts complete

        // ---- phase A: distributed partial dot (all 1024 threads) ----
        {
            const int g = tid >> 6, c = tid & 63;    // strip j = 4g..4g+3
            float f0, f1, f2, f3;
            if (fast) {
                unsigned u = cnt[buf][g];
                f0 = __uint_as_float(__byte_perm(u, 0x4B000000u, 0x7540)) - 8388608.0f;
                f1 = __uint_as_float(__byte_perm(u, 0x4B000000u, 0x7541)) - 8388608.0f;
                f2 = __uint_as_float(__byte_perm(u, 0x4B000000u, 0x7542)) - 8388608.0f;
                f3 = __uint_as_float(__byte_perm(u, 0x4B000000u, 0x7543)) - 8388608.0f;
            } else {
                f0 = cf_slow[buf][4 * g + 0];
                f1 = cf_slow[buf][4 * g + 1];
                f2 = cf_slow[buf][4 * g + 2];
                f3 = cf_slow[buf][4 * g + 3];
            }
            const float* wr = &Wts[(4 * g) * NC + c];
            partial[g][c] = (f0 * wr[0] + f1 * wr[NC]) + (f2 * wr[2 * NC] + f3 * wr[3 * NC]);

            if (tid < 16)  cnt[buf ^ 1][tid] = 0u;       // consumed 2 syncs ago
            if (tid < 64)  cf_slow[buf ^ 1][tid] = 0.0f;
        }

        __syncthreads();   // partials ready

        // ---- phase B: 64-thread combine ----
        if (tid < NC) {
            float a0 = 0.f, a1 = 0.f, a2 = 0.f, a3 = 0.f;
            #pragma unroll
            for (int g = 0; g < 16; g += 4) {
                a0 += partial[g + 0][tid];
                a1 += partial[g + 1][tid];
                a2 += partial[g + 2][tid];
                a3 += partial[g + 3][tid];
            }
            ns[tid] = ((a0 + a1) + (a2 + a3)) * g_sm[tid];
        }

        __syncthreads();   // ns ready

        // ---- apply cascade to i_syn ----
        if (fast) {
            float4 nsv = *(const float4*)&ns[4 * (tid & 15)];
            isyn[0] += nsv.x; isyn[1] += nsv.y; isyn[2] += nsv.z; isyn[3] += nsv.w;
            isyn[4] += nsv.x; isyn[5] += nsv.y; isyn[6] += nsv.z; isyn[7] += nsv.w;
        } else {
            #pragma unroll
            for (int k = 0; k < 8; k++) {
                int d = 4 * tid + (k & 3) + (k >> 2) * 4096;
                isyn[k] += ns[__ldg(&cids[d])];
            }
        }
    }
}

extern "C" void kernel_launch(void* const* d_in, const int* in_sizes, int n_in,
                              void* d_out, int out_size)
{
    const float* x      = (const float*)d_in[0];   // current_in [T,B,D]
    const float* th_raw = (const float*)d_in[1];   // threshold_raw [D]
    const float* bm_raw = (const float*)d_in[2];   // beta_mem_raw
    const float* bs_raw = (const float*)d_in[3];   // beta_syn_raw
    const float* nw     = (const float*)d_in[4];   // neighbor_weights [NC,NC]
    const float* gain   = (const float*)d_in[5];   // cluster_gain [NC]
    const int*   cids   = (const int*)d_in[6];     // cluster_ids [D]

    float* out_s = (float*)d_out;
    float* out_v = out_s + (size_t)T_STEPS * BATCH * DIM;

    assoc_lif_kernel<<<BATCH, TPB>>>(x, th_raw, bm_raw, bs_raw, nw, gain, cids,
                                     out_s, out_v);
}